// round 15
// baseline (speedup 1.0000x reference)
#include <cuda_runtime.h>
#include <stdint.h>

#define NB 8
#define NO 64
#define NT 251
#define NL 48000
#define NT1 3000   /* NL/16 level-1 tiles */
#define NT2 188
#define NT3 12
#define TPB_CHUNK 32          /* tiles per synth block */
#define NCHUNK 94             /* ceil(3000/32) */
#define NOG 8                 /* o-groups (one per warp) */
#define OPG 8                 /* harmonics per group */
#define FR 6                  /* staged frames per chunk */
#define PSTRIDE 17            /* per-tile partial stride (odd -> conflict-free) */
#define POG (TPB_CHUNK * PSTRIDE)   /* 544 floats per og */

// ---------------- device scratch (static, no runtime alloc) ----------------
__device__ float g_S1[NB * NO * NT1];   // per-(b,o) inclusive tile-prefix sums
__device__ float g_A[NB * NO * NT];     // normalized amps * master

// exact f32 constants matching the reference's rounding
#define C1F ((float)(2.0 * 3.14159265358979323846 / 48000.0))
#define C2F ((float)(250.0 / 47999.0))
#define PIF ((float)3.14159265358979323846)

// Cody-Waite split of 2*pi (kf <= 2^17 keeps the first three FMA steps exact).
#define TWOPI_A 6.28125f
#define TWOPI_B 1.93023681640625e-3f
#define TWOPI_C 5.0663948059082031e-6f
#define TWOPI_D 3.9683744e-9f
#define INV2PI_F 0.15915494309189533577f

// ---------------- K0: amps once per (b,t) for all o ----------------
__global__ void __launch_bounds__(256)
amps_kernel(const float* __restrict__ f0,
            const float* __restrict__ master,
            const float* __restrict__ ov) {
    int b = blockIdx.x;
    for (int t = threadIdx.x; t < NT; t += 256) {
        float w = __fmul_rn(f0[b * NT + t], C1F);
        float s = 0.0f;
        for (int oo = 0; oo < NO; oo++) {
            float fsv = __fmul_rn(w, (float)(oo + 1));
            float a = (fsv > PIF) ? 0.0f : ov[((size_t)(b * NO + oo)) * NT + t];
            s = __fadd_rn(s, a);
        }
        float m = master[b * NT + t];
        for (int o = 0; o < NO; o++) {
            float fsv = __fmul_rn(w, (float)(o + 1));
            float a = (fsv > PIF) ? 0.0f : ov[((size_t)(b * NO + o)) * NT + t];
            g_A[(b * NO + o) * NT + t] = __fmul_rn(__fdiv_rn(a, s), m);
        }
    }
}

// ---------------- K1: XLA blocked scan -> S1 (per b,o) ----------------
__global__ void __launch_bounds__(512)
scan_kernel(const float* __restrict__ f0) {
    __shared__ float buf[3392];     // ts1[0..3000) ts2@3000 S2@3188 S3@3376
    __shared__ float fs[256];
    float* ts1 = buf;
    float* ts2 = buf + 3000;
    float* S2  = buf + 3188;
    float* S3  = buf + 3376;

    int bo = blockIdx.x;
    int b = bo >> 6;
    int o = bo & 63;
    int tid = threadIdx.x;
    const int T = 512;
    float h = (float)(o + 1);

    if (tid < NT) {
        float w = __fmul_rn(f0[b * NT + tid], C1F);
        fs[tid] = __fmul_rn(w, h);
    }
    __syncthreads();

    auto fsup = [&](int l) -> float {
        float pos = __fmul_rn((float)l, C2F);
        int i0 = (int)floorf(pos);
        i0 = i0 < 0 ? 0 : (i0 > NT - 2 ? NT - 2 : i0);
        float fr = __fsub_rn(pos, (float)i0);
        return __fadd_rn(__fmul_rn(fs[i0], __fsub_rn(1.0f, fr)),
                         __fmul_rn(fs[i0 + 1], fr));
    };

    // Stage A: level-1 tile sums
    for (int j = tid; j < NT1; j += T) {
        float s = 0.0f;
        int base = j * 16;
#pragma unroll 4
        for (int i = 0; i < 16; i++) s = __fadd_rn(s, fsup(base + i));
        ts1[j] = s;
    }
    __syncthreads();
    // Stage B
    if (tid < NT2) {
        int k = tid;
        float s = 0.0f;
        int bgn = k * 16, end = bgn + 16 < NT1 ? bgn + 16 : NT1;
        for (int i = bgn; i < end; i++) s = __fadd_rn(s, ts1[i]);
        ts2[k] = s;
    }
    __syncthreads();
    // Stage C
    if (tid < NT3) {
        float s = 0.0f;
        int bgn = tid * 16, end = bgn + 16 < NT2 ? bgn + 16 : NT2;
        for (int i = bgn; i < end; i++) s = __fadd_rn(s, ts2[i]);
        S3[tid] = s;
    }
    __syncthreads();
    if (tid == 0) {
        float r = 0.0f;
        for (int p = 0; p < NT3; p++) { r = __fadd_rn(r, S3[p]); S3[p] = r; }
    }
    __syncthreads();
    // Stage D
    if (tid < NT2) {
        int t = tid, p = t >> 4, m = t & 15;
        float s = 0.0f;
        int bgn = p * 16;
        for (int i = 0; i <= m; i++) s = __fadd_rn(s, ts2[bgn + i]);
        float off = p ? S3[p - 1] : 0.0f;
        S2[t] = __fadd_rn(off, s);
    }
    __syncthreads();
    // Stage E + write-out
    for (int t = tid; t < NT1; t += T) {
        int k = t >> 4, m = t & 15;
        float s = 0.0f;
        int bgn = k * 16;
        for (int i = 0; i <= m; i++) s = __fadd_rn(s, ts1[bgn + i]);
        float off = k ? S2[k - 1] : 0.0f;
        g_S1[bo * NT1 + t] = __fadd_rn(off, s);
    }
}

// ---------------- K2: fused synthesis + harmonic reduction ----------------
// block = (b, 32-tile chunk), 256 threads = 8 warps.
// warp = o-group (warp-uniform), lane = tile -> per-o smem reads are
// broadcasts/stride-1 (conflict-free). Branchless sin via Cody-Waite 2pi
// reduction + MUFU __sinf (accuracy budget: 3.6e-7 << 1e-3).
__global__ void __launch_bounds__(256)
synth_kernel(const float* __restrict__ f0, float* __restrict__ out) {
    __shared__ float S1s[NO * (TPB_CHUNK + 1)];   // [o][jj] 8.4KB
    __shared__ float Ars[NO * FR];                // [o][fi] warp-uniform reads
    __shared__ float Fss[NO * FR];                // [o][fi] = fmul(w[fi], h)
    __shared__ float part[NOG * POG];             // [og][tile*17+i] 17.4KB

    int blk = blockIdx.x;
    int b = blk / NCHUNK;
    int chunk = blk - b * NCHUNK;
    int j0 = chunk * TPB_CHUNK;
    int tid = threadIdx.x;

    // frame base for this chunk
    int l0 = j0 * 16;
    float pos0 = __fmul_rn((float)l0, C2F);
    int fb = (int)floorf(pos0);
    fb = fb < 0 ? 0 : (fb > NT - 2 ? NT - 2 : fb);

    for (int idx = tid; idx < NO * FR; idx += 256) {
        int o = idx / FR, ff = idx - o * FR;
        int f = fb + ff;
        float w = (f < NT) ? __fmul_rn(f0[b * NT + f], C1F) : 0.0f;
        Fss[idx] = __fmul_rn(w, (float)(o + 1));     // same ops as fs in scan
        Ars[idx] = (f < NT) ? g_A[(b * NO + o) * NT + f] : 0.0f;
    }
    for (int idx = tid; idx < NO * (TPB_CHUNK + 1); idx += 256) {
        int o = idx / (TPB_CHUNK + 1), jj = idx - o * (TPB_CHUNK + 1);
        int j = j0 - 1 + jj;
        S1s[idx] = (j >= 0 && j < NT1) ? g_S1[(b * NO + o) * NT1 + j] : 0.0f;
    }
    __syncthreads();

    int og = tid >> 5;            // warp id = o-group
    int lane = tid & 31;          // lane = tile within chunk
    int obase = og * OPG;
    int j = j0 + lane;
    bool valid = (j < NT1);

    // warp-uniform skip of fully-aliased o-groups
    bool anyamp = false;
#pragma unroll
    for (int oo = 0; oo < OPG; oo++)
#pragma unroll
        for (int ff = 0; ff < FR; ff++)
            anyamp |= (Ars[(obase + oo) * FR + ff] != 0.0f);
    bool active = valid && anyamp;

    float off[OPG], run[OPG];
#pragma unroll
    for (int oo = 0; oo < OPG; oo++) {
        off[oo] = (j == 0) ? 0.0f
                : S1s[(obase + oo) * (TPB_CHUNK + 1) + lane];
        run[oo] = 0.0f;
    }

#pragma unroll 1
    for (int i = 0; i < 16; i++) {
        float accs = 0.0f;
        if (active) {
            int l = j * 16 + i;
            float pos = __fmul_rn((float)l, C2F);
            int i0 = (int)floorf(pos);
            i0 = i0 < 0 ? 0 : (i0 > NT - 2 ? NT - 2 : i0);
            float fr = __fsub_rn(pos, (float)i0);
            float omf = __fsub_rn(1.0f, fr);
            int fi = i0 - fb;
#pragma unroll
            for (int oo = 0; oo < OPG; oo++) {
                float f0v = Fss[(obase + oo) * FR + fi];
                float f1v = Fss[(obase + oo) * FR + fi + 1];
                float f = __fadd_rn(__fmul_rn(f0v, omf), __fmul_rn(f1v, fr));
                run[oo] = __fadd_rn(run[oo], f);
                float ph = __fadd_rn(off[oo], run[oo]);
                float a0 = Ars[(obase + oo) * FR + fi];
                float a1 = Ars[(obase + oo) * FR + fi + 1];
                float amp = __fadd_rn(__fmul_rn(a0, omf), __fmul_rn(a1, fr));
                // mod 2*pi (exact Cody-Waite), then MUFU sin on [-pi, pi]
                float kf = rintf(__fmul_rn(ph, INV2PI_F));
                float r = __fmaf_rn(-kf, TWOPI_A, ph);
                r = __fmaf_rn(-kf, TWOPI_B, r);
                r = __fmaf_rn(-kf, TWOPI_C, r);
                r = __fmaf_rn(-kf, TWOPI_D, r);
                float sv = __sinf(r);
                accs = __fadd_rn(accs, __fmul_rn(sv, amp));
            }
        }
        part[og * POG + lane * PSTRIDE + i] = accs;   // stride 17: conflict-free
    }
    __syncthreads();

    // deterministic reduction over og (ascending), coalesced output
#pragma unroll
    for (int s = tid; s < TPB_CHUNK * 16; s += 256) {
        int lg = l0 + s;
        if (lg < NL) {
            int tile = s >> 4, ii = s & 15;
            int base = tile * PSTRIDE + ii;
            float r = 0.0f;
#pragma unroll
            for (int g = 0; g < NOG; g++)
                r = __fadd_rn(r, part[g * POG + base]);
            out[b * NL + lg] = r;
        }
    }
}

// ---------------- launch ----------------
extern "C" void kernel_launch(void* const* d_in, const int* in_sizes, int n_in,
                              void* d_out, int out_size) {
    const float* f0     = (const float*)d_in[0];
    const float* master = (const float*)d_in[1];
    const float* ov     = (const float*)d_in[2];
    float* out = (float*)d_out;

    amps_kernel<<<NB, 256>>>(f0, master, ov);
    scan_kernel<<<NB * NO, 512>>>(f0);
    synth_kernel<<<NB * NCHUNK, 256>>>(f0, out);
}

// round 16
// speedup vs baseline: 1.1756x; 1.1756x over previous
#include <cuda_runtime.h>
#include <stdint.h>

#define NB 8
#define NO 64
#define NT 251
#define NL 48000
#define NT1 3000   /* NL/16 level-1 tiles */
#define NT2 188
#define NT3 12
#define TPB_CHUNK 32          /* tiles per synth block */
#define NCHUNK 94             /* ceil(3000/32) */
#define NOG 8                 /* o-groups (one per warp) */
#define OPG 8                 /* harmonics per group */
#define FR 6                  /* staged frames per chunk */
#define PSTRIDE 17            /* per-tile partial stride (odd -> conflict-free) */
#define POG (TPB_CHUNK * PSTRIDE)   /* 544 floats per og */

// ---------------- device scratch (static, no runtime alloc) ----------------
__device__ float g_S1[NB * NO * NT1];   // per-(b,o) inclusive tile-prefix sums

// exact f32 constants matching the reference's rounding
#define C1F ((float)(2.0 * 3.14159265358979323846 / 48000.0))
#define C2F ((float)(250.0 / 47999.0))
#define PIF ((float)3.14159265358979323846)

// Cody-Waite split of 2*pi (kf <= 2^17 keeps the first three FMA steps exact).
#define TWOPI_A 6.28125f
#define TWOPI_B 1.93023681640625e-3f
#define TWOPI_C 5.0663948059082031e-6f
#define TWOPI_D 3.9683744e-9f
#define INV2PI_F 0.15915494309189533577f

// ---------------- K1: XLA blocked scan -> S1 (per b,o) ----------------
__global__ void __launch_bounds__(512)
scan_kernel(const float* __restrict__ f0) {
    __shared__ float buf[3392];     // ts1[0..3000) ts2@3000 S2@3188 S3@3376
    __shared__ float fs[256];
    float* ts1 = buf;
    float* ts2 = buf + 3000;
    float* S2  = buf + 3188;
    float* S3  = buf + 3376;

    int bo = blockIdx.x;
    int b = bo >> 6;
    int o = bo & 63;
    int tid = threadIdx.x;
    const int T = 512;
    float h = (float)(o + 1);

    if (tid < NT) {
        float w = __fmul_rn(f0[b * NT + tid], C1F);
        fs[tid] = __fmul_rn(w, h);
    }
    __syncthreads();

    auto fsup = [&](int l) -> float {
        float pos = __fmul_rn((float)l, C2F);
        int i0 = (int)floorf(pos);
        i0 = i0 < 0 ? 0 : (i0 > NT - 2 ? NT - 2 : i0);
        float fr = __fsub_rn(pos, (float)i0);
        return __fadd_rn(__fmul_rn(fs[i0], __fsub_rn(1.0f, fr)),
                         __fmul_rn(fs[i0 + 1], fr));
    };

    // Stage A: level-1 tile sums
    for (int j = tid; j < NT1; j += T) {
        float s = 0.0f;
        int base = j * 16;
#pragma unroll 4
        for (int i = 0; i < 16; i++) s = __fadd_rn(s, fsup(base + i));
        ts1[j] = s;
    }
    __syncthreads();
    // Stage B
    if (tid < NT2) {
        int k = tid;
        float s = 0.0f;
        int bgn = k * 16, end = bgn + 16 < NT1 ? bgn + 16 : NT1;
        for (int i = bgn; i < end; i++) s = __fadd_rn(s, ts1[i]);
        ts2[k] = s;
    }
    __syncthreads();
    // Stage C
    if (tid < NT3) {
        float s = 0.0f;
        int bgn = tid * 16, end = bgn + 16 < NT2 ? bgn + 16 : NT2;
        for (int i = bgn; i < end; i++) s = __fadd_rn(s, ts2[i]);
        S3[tid] = s;
    }
    __syncthreads();
    if (tid == 0) {
        float r = 0.0f;
        for (int p = 0; p < NT3; p++) { r = __fadd_rn(r, S3[p]); S3[p] = r; }
    }
    __syncthreads();
    // Stage D
    if (tid < NT2) {
        int t = tid, p = t >> 4, m = t & 15;
        float s = 0.0f;
        int bgn = p * 16;
        for (int i = 0; i <= m; i++) s = __fadd_rn(s, ts2[bgn + i]);
        float off = p ? S3[p - 1] : 0.0f;
        S2[t] = __fadd_rn(off, s);
    }
    __syncthreads();
    // Stage E + write-out
    for (int t = tid; t < NT1; t += T) {
        int k = t >> 4, m = t & 15;
        float s = 0.0f;
        int bgn = k * 16;
        for (int i = 0; i <= m; i++) s = __fadd_rn(s, ts1[bgn + i]);
        float off = k ? S2[k - 1] : 0.0f;
        g_S1[bo * NT1 + t] = __fadd_rn(off, s);
    }
}

// ---------------- K2: fused amps + synthesis + harmonic reduction ----------------
// block = (b, 32-tile chunk), 256 threads = 8 warps.
// warp = o-group (warp-uniform), lane = tile. Amps for the chunk's <=6 frames
// are computed in-block (exact reference op order, bit-identical).
__global__ void __launch_bounds__(256)
synth_kernel(const float* __restrict__ f0,
             const float* __restrict__ master,
             const float* __restrict__ ov,
             float* __restrict__ out) {
    __shared__ float S1s[NO * (TPB_CHUNK + 1)];   // [o][jj] 8.4KB
    __shared__ float Ars[NO * FR];                // [o][fi] warp-uniform reads
    __shared__ float Fss[NO * FR];                // [o][fi] = fmul(w[fi], h)
    __shared__ float part[NOG * POG];             // [og][tile*17+i] 17.4KB
    __shared__ float ssum[FR], wsh[FR], msh[FR];

    int blk = blockIdx.x;
    int b = blk / NCHUNK;
    int chunk = blk - b * NCHUNK;
    int j0 = chunk * TPB_CHUNK;
    int tid = threadIdx.x;

    // frame base for this chunk
    int l0 = j0 * 16;
    float pos0 = __fmul_rn((float)l0, C2F);
    int fb = (int)floorf(pos0);
    fb = fb < 0 ? 0 : (fb > NT - 2 ? NT - 2 : fb);

    // per-frame masked harmonic sum (exact oo-ascending fold, 6 threads)
    if (tid < FR) {
        int f = fb + tid;
        if (f < NT) {
            float w = __fmul_rn(f0[b * NT + f], C1F);
            float s = 0.0f;
            for (int oo = 0; oo < NO; oo++) {
                float fsv = __fmul_rn(w, (float)(oo + 1));
                float a = (fsv > PIF) ? 0.0f
                        : ov[((size_t)(b * NO + oo)) * NT + f];
                s = __fadd_rn(s, a);
            }
            wsh[tid] = w;
            ssum[tid] = s;
            msh[tid] = master[b * NT + f];
        } else {
            wsh[tid] = 0.0f; ssum[tid] = 1.0f; msh[tid] = 0.0f;
        }
    }
    // stage S1 slice meanwhile
    for (int idx = tid; idx < NO * (TPB_CHUNK + 1); idx += 256) {
        int o = idx / (TPB_CHUNK + 1), jj = idx - o * (TPB_CHUNK + 1);
        int j = j0 - 1 + jj;
        S1s[idx] = (j >= 0 && j < NT1) ? g_S1[(b * NO + o) * NT1 + j] : 0.0f;
    }
    __syncthreads();

    // amps + harmonic freqs for this chunk's frames (exact reference ops)
    for (int idx = tid; idx < NO * FR; idx += 256) {
        int o = idx / FR, ff = idx - o * FR;
        int f = fb + ff;
        float w = wsh[ff];
        float fso = __fmul_rn(w, (float)(o + 1));
        Fss[idx] = fso;
        float a = 0.0f;
        if (f < NT) {
            a = (fso > PIF) ? 0.0f : ov[((size_t)(b * NO + o)) * NT + f];
        }
        Ars[idx] = __fmul_rn(__fdiv_rn(a, ssum[ff]), msh[ff]);
    }
    __syncthreads();

    int og = tid >> 5;            // warp id = o-group
    int lane = tid & 31;          // lane = tile within chunk
    int obase = og * OPG;
    int j = j0 + lane;
    bool valid = (j < NT1);

    // warp-uniform skip of fully-aliased o-groups
    bool anyamp = false;
#pragma unroll
    for (int oo = 0; oo < OPG; oo++)
#pragma unroll
        for (int ff = 0; ff < FR; ff++)
            anyamp |= (Ars[(obase + oo) * FR + ff] != 0.0f);
    bool active = valid && anyamp;

    float off[OPG], run[OPG];
#pragma unroll
    for (int oo = 0; oo < OPG; oo++) {
        off[oo] = (j == 0) ? 0.0f
                : S1s[(obase + oo) * (TPB_CHUNK + 1) + lane];
        run[oo] = 0.0f;
    }

#pragma unroll 1
    for (int i = 0; i < 16; i++) {
        float accs = 0.0f;
        if (active) {
            int l = j * 16 + i;
            float pos = __fmul_rn((float)l, C2F);
            int i0 = (int)floorf(pos);
            i0 = i0 < 0 ? 0 : (i0 > NT - 2 ? NT - 2 : i0);
            float fr = __fsub_rn(pos, (float)i0);
            float omf = __fsub_rn(1.0f, fr);
            int fi = i0 - fb;
#pragma unroll
            for (int oo = 0; oo < OPG; oo++) {
                float f0v = Fss[(obase + oo) * FR + fi];
                float f1v = Fss[(obase + oo) * FR + fi + 1];
                float f = __fadd_rn(__fmul_rn(f0v, omf), __fmul_rn(f1v, fr));
                run[oo] = __fadd_rn(run[oo], f);
                float ph = __fadd_rn(off[oo], run[oo]);
                float a0 = Ars[(obase + oo) * FR + fi];
                float a1 = Ars[(obase + oo) * FR + fi + 1];
                float amp = __fadd_rn(__fmul_rn(a0, omf), __fmul_rn(a1, fr));
                // mod 2*pi (exact Cody-Waite), then MUFU sin on [-pi, pi]
                float kf = rintf(__fmul_rn(ph, INV2PI_F));
                float r = __fmaf_rn(-kf, TWOPI_A, ph);
                r = __fmaf_rn(-kf, TWOPI_B, r);
                r = __fmaf_rn(-kf, TWOPI_C, r);
                r = __fmaf_rn(-kf, TWOPI_D, r);
                float sv = __sinf(r);
                accs = __fadd_rn(accs, __fmul_rn(sv, amp));
            }
        }
        part[og * POG + lane * PSTRIDE + i] = accs;   // stride 17: conflict-free
    }
    __syncthreads();

    // deterministic reduction over og (ascending), coalesced output
#pragma unroll
    for (int s = tid; s < TPB_CHUNK * 16; s += 256) {
        int lg = l0 + s;
        if (lg < NL) {
            int tile = s >> 4, ii = s & 15;
            int base = tile * PSTRIDE + ii;
            float r = 0.0f;
#pragma unroll
            for (int g = 0; g < NOG; g++)
                r = __fadd_rn(r, part[g * POG + base]);
            out[b * NL + lg] = r;
        }
    }
}

// ---------------- launch ----------------
extern "C" void kernel_launch(void* const* d_in, const int* in_sizes, int n_in,
                              void* d_out, int out_size) {
    const float* f0     = (const float*)d_in[0];
    const float* master = (const float*)d_in[1];
    const float* ov     = (const float*)d_in[2];
    float* out = (float*)d_out;

    scan_kernel<<<NB * NO, 512>>>(f0);
    synth_kernel<<<NB * NCHUNK, 256>>>(f0, master, ov, out);
}